// round 5
// baseline (speedup 1.0000x reference)
#include <cuda_runtime.h>
#include <cstdint>
#include <math_constants.h>

#define T_STEPS 100
#define U_UNITS 16
#define N_NEUR  1024
#define H_DIM   128
#define NBLK    148
#define NTHR    1024

// ---------------- scratch (device globals; no allocation) ----------------
__device__ float   g_cur[U_UNITS * T_STEPS * N_NEUR];
__device__ uint8_t g_z[U_UNITS * T_STEPS * N_NEUR];
__device__ float   g_act[U_UNITS * N_NEUR];
__device__ float   g_h[H_DIM];
__device__ float   g_conn[U_UNITS * U_UNITS];
__device__ int     g_spk[U_UNITS];
__device__ int     g_spk_total;
__device__ float   g_partialA[NBLK];     // per-block max row-L1 of w_in
__device__ float   g_partialB[NBLK];     // per-block max |input|
// software grid barrier state (epoch-based; replay-safe: epoch only grows)
__device__ int     g_bar_count = 0;
__device__ int     g_bar_epoch = 0;

// ---------------- grid barrier (all NBLK blocks co-resident) ----------------
__device__ __forceinline__ void grid_barrier() {
    __syncthreads();
    if (threadIdx.x == 0) {
        __threadfence();
        int e = *(volatile int*)&g_bar_epoch;
        int t = atomicAdd(&g_bar_count, 1);
        if (t == NBLK - 1) {
            g_bar_count = 0;
            __threadfence();
            atomicAdd(&g_bar_epoch, 1);
        } else {
            while (*(volatile int*)&g_bar_epoch == e) { }
        }
        __threadfence();
    }
    __syncthreads();
}

// ---------------- threefry2x32 (JAX-compatible) ----------------
__device__ __forceinline__ uint32_t rotl32(uint32_t x, int d) {
    return (x << d) | (x >> (32 - d));
}
__device__ __forceinline__ void threefry2x32(uint32_t k0, uint32_t k1,
                                             uint32_t x0, uint32_t x1,
                                             uint32_t& o0, uint32_t& o1) {
    uint32_t ks[3] = {k0, k1, k0 ^ k1 ^ 0x1BD11BDAu};
    x0 += ks[0]; x1 += ks[1];
    const int R[2][4] = {{13, 15, 26, 6}, {17, 29, 16, 24}};
    #pragma unroll
    for (int i = 0; i < 5; i++) {
        const int* r = R[i & 1];
        #pragma unroll
        for (int j = 0; j < 4; j++) {
            x0 += x1; x1 = rotl32(x1, r[j]); x1 ^= x0;
        }
        x0 += ks[(i + 1) % 3];
        x1 += ks[(i + 2) % 3] + (uint32_t)(i + 1);
    }
    o0 = x0; o1 = x1;
}

// ============================ THE mega-kernel ============================
__global__ void __launch_bounds__(NTHR, 1)
mega(const float* __restrict__ spikes, const float* __restrict__ w_in,
     const float* __restrict__ w_rec,  const float* __restrict__ unit_w,
     const float* __restrict__ cw1,    const float* __restrict__ cb1,
     const float* __restrict__ cw2,    const float* __restrict__ cb2,
     float* __restrict__ out) {
    const int tid  = threadIdx.x;
    const int bid  = blockIdx.x;
    const int warp = tid >> 5, lane = tid & 31;
    const int gtid = bid * NTHR + tid;

    __shared__ float smA[32], smB[32];
    __shared__ float s_red[32];

    // -------- speculative skip-path output + input max (overlapped) --------
    // Safe: if we end up in the fallback, Phase F rewrites every out element.
    float xmax = 0.0f;
    if (gtid < (T_STEPS * N_NEUR) / 4) {
        float4 v = reinterpret_cast<const float4*>(spikes)[gtid];
        float4 o;
        o.x = 1.5f * v.x; o.y = 1.5f * v.y; o.z = 1.5f * v.z; o.w = 1.5f * v.w;
        reinterpret_cast<float4*>(out)[gtid] = o;
        xmax = fmaxf(fmaxf(fabsf(v.x), fabsf(v.y)), fmaxf(fabsf(v.z), fabsf(v.w)));
        // NaN in spikes is benign for the proof: NaN currents can never
        // satisfy (v - VTH) > 0, so z==0 and out = 1.5*spikes either way.
    }

    // -------- Phase A: streamed max-row-L1 of w_in (no shfl in load loop) ----
    // One 4-row tile per warp: 8 lanes/row, 32 float4/lane, all loads independent.
    float wmax = 0.0f;
    {
        const int tile = warp * NBLK + bid;          // balanced across blocks
        if (tile < (U_UNITS * N_NEUR) / 4) {         // 4096 tiles
            const int row = tile * 4 + (lane >> 3);
            const float4* rp = reinterpret_cast<const float4*>(
                                   w_in + (size_t)row * N_NEUR) + (lane & 7);
            float a0 = 0.f, a1 = 0.f, a2 = 0.f, a3 = 0.f;
            #pragma unroll
            for (int i = 0; i < 32; i += 4) {
                float4 x0 = __ldcs(rp + 8 * (i + 0));
                float4 x1 = __ldcs(rp + 8 * (i + 1));
                float4 x2 = __ldcs(rp + 8 * (i + 2));
                float4 x3 = __ldcs(rp + 8 * (i + 3));
                a0 += fabsf(x0.x) + fabsf(x0.y) + fabsf(x0.z) + fabsf(x0.w);
                a1 += fabsf(x1.x) + fabsf(x1.y) + fabsf(x1.z) + fabsf(x1.w);
                a2 += fabsf(x2.x) + fabsf(x2.y) + fabsf(x2.z) + fabsf(x2.w);
                a3 += fabsf(x3.x) + fabsf(x3.y) + fabsf(x3.z) + fabsf(x3.w);
            }
            float s = (a0 + a1) + (a2 + a3);
            // reduce within each 8-lane row group (lanes 0,8,16,24 -> row sums)
            s += __shfl_down_sync(0xFFFFFFFFu, s, 4);
            s += __shfl_down_sync(0xFFFFFFFFu, s, 2);
            s += __shfl_down_sync(0xFFFFFFFFu, s, 1);
            if (!(s == s)) s = CUDART_INF_F;         // NaN => force fallback
            float r0 = __shfl_sync(0xFFFFFFFFu, s, 0);
            float r1 = __shfl_sync(0xFFFFFFFFu, s, 8);
            float r2 = __shfl_sync(0xFFFFFFFFu, s, 16);
            float r3 = __shfl_sync(0xFFFFFFFFu, s, 24);
            wmax = fmaxf(fmaxf(r0, r1), fmaxf(r2, r3));
        }
    }

    // block-level reduction of wmax / xmax
    #pragma unroll
    for (int o = 16; o > 0; o >>= 1)
        xmax = fmaxf(xmax, __shfl_down_sync(0xFFFFFFFFu, xmax, o));
    if (lane == 0) { smA[warp] = wmax; smB[warp] = xmax; }
    __syncthreads();
    if (tid == 0) {
        float A = 0.0f, B = 0.0f;
        #pragma unroll
        for (int w = 0; w < 32; w++) { A = fmaxf(A, smA[w]); B = fmaxf(B, smB[w]); }
        g_partialA[bid] = A;
        g_partialB[bid] = B;
    }

    grid_barrier();

    // every block redundantly reduces the 148 partials -> identical skip decision
    __shared__ int s_skip;
    {
        float A = 0.0f, B = 0.0f;
        if (tid < NBLK) { A = g_partialA[tid]; B = g_partialB[tid]; }
        #pragma unroll
        for (int o = 16; o > 0; o >>= 1) {
            A = fmaxf(A, __shfl_down_sync(0xFFFFFFFFu, A, o));
            B = fmaxf(B, __shfl_down_sync(0xFFFFFFFFu, B, o));
        }
        if (lane == 0) { smA[warp] = A; smB[warp] = B; }
        __syncthreads();
        if (tid == 0) {
            float L1 = 0.0f, X = 0.0f;
            #pragma unroll
            for (int w = 0; w < 5; w++) { L1 = fmaxf(L1, smA[w]); X = fmaxf(X, smB[w]); }
            // Until the first spike z==0, so |i_t| <= t*X*L1 and
            // v_T - V_LEAK <= 5e-5 * 4950 * X * L1.  If < 14 << 15 = VTH-VLEAK,
            // no neuron can ever spike. NaN rows were mapped to INF above.
            float bound = 5e-5f * 4950.0f * X * L1;
            s_skip = (bound < 14.0f) ? 1 : 0;
        }
        __syncthreads();
    }

    // skip: output was already written speculatively
    if (s_skip) return;

    // ================= Fallback path (correctness only) =================

    // ---- Phase B: input-current GEMM cur[u,t,n] = spikes[t,:].w_in[u,n,:] ----
    for (int idx = gtid; idx < U_UNITS * T_STEPS * N_NEUR; idx += NBLK * NTHR) {
        int u = idx / (T_STEPS * N_NEUR);
        int r = idx % (T_STEPS * N_NEUR);
        int t = r / N_NEUR, n = r % N_NEUR;
        const float* sp = spikes + (size_t)t * N_NEUR;
        const float* wr = w_in + ((size_t)u * N_NEUR + n) * N_NEUR;
        float acc = 0.0f;
        #pragma unroll 4
        for (int k = 0; k < N_NEUR; k++) acc += sp[k] * wr[k];
        g_cur[idx] = acc;
    }

    grid_barrier();

    // ---- Phase C: LIF recurrent scan, blocks 0..15 each own a unit ----
    {
        __shared__ unsigned mask[32];
        __shared__ int s_total;
        if (bid < U_UNITS) {
            const int u = bid, n = tid;
            if (n == 0) s_total = 0;
            const float DTM = 5e-5f, DEC = 1.0f - 1e-4f;
            const float VLEAK = -70.0f, VTH = -55.0f, VRST = -70.0f;
            float v = VLEAK, i_syn = 0.0f;
            int count_prev = 0, emitted = 0;
            const float* wr   = w_rec + ((size_t)u * N_NEUR + n) * N_NEUR;
            const float* curp = g_cur + (size_t)u * T_STEPS * N_NEUR + n;
            uint8_t*     zp   = g_z   + (size_t)u * T_STEPS * N_NEUR + n;
            float cur_t = curp[0];
            __syncthreads();
            for (int t = 0; t < T_STEPS; t++) {
                float v_dec = v + DTM * ((VLEAK - v) + i_syn);
                float i_dec = i_syn * DEC;
                bool  z     = (v_dec - VTH) > 0.0f;
                v = z ? VRST : v_dec;
                emitted += (int)z;
                zp[t * N_NEUR] = z ? (uint8_t)1 : (uint8_t)0;
                float rec = 0.0f;
                if (count_prev > 0) {
                    #pragma unroll 1
                    for (int w = 0; w < 32; w++) {
                        unsigned m = mask[w];
                        while (m) {
                            int b = __ffs(m) - 1;
                            rec += wr[w * 32 + b];
                            m &= m - 1;
                        }
                    }
                }
                i_syn = i_dec + cur_t + rec;
                float cur_next = (t + 1 < T_STEPS) ? curp[(t + 1) * N_NEUR] : 0.0f;
                __syncthreads();
                unsigned bal = __ballot_sync(0xFFFFFFFFu, z);
                if (lane == 0) mask[warp] = bal;
                __syncthreads();
                count_prev = 0;
                #pragma unroll
                for (int w = 0; w < 32; w++) count_prev += __popc(mask[w]);
                cur_t = cur_next;
            }
            g_act[u * N_NEUR + n] = (float)emitted * (1.0f / T_STEPS);
            atomicAdd(&s_total, emitted);
            __syncthreads();
            if (n == 0) g_spk[u] = s_total;
        }
    }

    grid_barrier();

    // ---- Phase D: hidden layer h = relu(act @ cw1.T + cb1), blocks 0..127 ----
    if (bid < H_DIM) {
        const float* row = cw1 + (size_t)bid * (U_UNITS * N_NEUR);
        float s = 0.0f;
        for (int j = tid; j < U_UNITS * N_NEUR; j += NTHR) s += row[j] * g_act[j];
        #pragma unroll
        for (int o = 16; o > 0; o >>= 1) s += __shfl_down_sync(0xFFFFFFFFu, s, o);
        if (lane == 0) s_red[warp] = s;
        __syncthreads();
        if (tid == 0) {
            float v = 0.0f;
            #pragma unroll
            for (int w = 0; w < 32; w++) v += s_red[w];
            g_h[bid] = fmaxf(v + cb1[bid], 0.0f);
        }
    }

    grid_barrier();

    // ---- Phase E: conn matrix + spike total, block 0 ----
    if (bid == 0) {
        __shared__ float hs[H_DIM];
        if (tid < H_DIM) hs[tid] = g_h[tid];
        __syncthreads();
        if (tid < U_UNITS * U_UNITS) {
            const int j = tid;
            float logit = cb2[j];
            const float* row = cw2 + (size_t)j * H_DIM;
            #pragma unroll 4
            for (int k = 0; k < H_DIM; k++) logit += hs[k] * row[k];
            float p = 1.0f / (1.0f + expf(-logit));
            uint32_t c = (j < 128) ? (uint32_t)j : (uint32_t)(j - 128);
            uint32_t o0, o1;
            threefry2x32(0u, 42u, c, c + 128u, o0, o1);
            uint32_t bits = (j < 128) ? o0 : o1;
            float uf = __uint_as_float((bits >> 9) | 0x3F800000u) - 1.0f;
            uf = fmaxf(uf, 0.0f);
            g_conn[j] = (uf < p) ? 1.0f : 0.0f;
            if (j == 0) {
                int tot = 0;
                #pragma unroll
                for (int u2 = 0; u2 < U_UNITS; u2++) tot += g_spk[u2];
                g_spk_total = tot;
            }
        }
    }

    grid_barrier();

    // ---- Phase F: routed/applied/combined + residual ----
    {
        const int zero = (g_spk_total == 0);
        for (int idx = gtid; idx < T_STEPS * N_NEUR; idx += NBLK * NTHR) {
            int t = idx / N_NEUR, m = idx % N_NEUR;
            float c = 0.0f;
            if (!zero) {
                for (int j = 0; j < U_UNITS; j++) {
                    float cj = 0.0f;
                    for (int nn = 0; nn < N_NEUR; nn++) {
                        float r = 0.0f;
                        #pragma unroll
                        for (int i2 = 0; i2 < U_UNITS; i2++)
                            r += g_conn[i2 * U_UNITS + j] *
                                 (float)g_z[((size_t)i2 * T_STEPS + t) * N_NEUR + nn];
                        cj += r * unit_w[((size_t)j * N_NEUR + nn) * N_NEUR + m];
                    }
                    c += cj;
                }
                c *= (1.0f / U_UNITS);
            }
            out[idx] = c + 1.5f * spikes[idx];
        }
    }
}

// ---------------- launch ----------------
extern "C" void kernel_launch(void* const* d_in, const int* in_sizes, int n_in,
                              void* d_out, int out_size) {
    const float* spikes = (const float*)d_in[0];
    const float* w_in   = (const float*)d_in[1];
    const float* w_rec  = (const float*)d_in[2];
    const float* unit_w = (const float*)d_in[3];
    const float* cw1    = (const float*)d_in[4];
    const float* cb1    = (const float*)d_in[5];
    const float* cw2    = (const float*)d_in[6];
    const float* cb2    = (const float*)d_in[7];
    float* out = (float*)d_out;

    mega<<<NBLK, NTHR>>>(spikes, w_in, w_rec, unit_w, cw1, cb1, cw2, cb2, out);
}

// round 6
// speedup vs baseline: 1.0175x; 1.0175x over previous
#include <cuda_runtime.h>
#include <cstdint>
#include <math_constants.h>

#define T_STEPS 100
#define U_UNITS 16
#define N_NEUR  1024
#define H_DIM   128
#define NBLK    148
#define NTHR    1024
#define NTHREADS_G (NBLK * NTHR)                    // 151552
#define W_TOT4  (U_UNITS * N_NEUR * N_NEUR / 4)     // 4194304 float4s

// ---------------- scratch (device globals; no allocation) ----------------
__device__ float   g_cur[U_UNITS * T_STEPS * N_NEUR];
__device__ uint8_t g_z[U_UNITS * T_STEPS * N_NEUR];
__device__ float   g_act[U_UNITS * N_NEUR];
__device__ float   g_h[H_DIM];
__device__ float   g_conn[U_UNITS * U_UNITS];
__device__ int     g_spk[U_UNITS];
__device__ int     g_spk_total;
__device__ float   g_partialA[NBLK];     // per-block max |w_in|
__device__ float   g_partialB[NBLK];     // per-block max |input|
// software grid barrier state (epoch-based; replay-safe: epoch only grows)
__device__ int     g_bar_count = 0;
__device__ int     g_bar_epoch = 0;

// ---------------- grid barrier (all NBLK blocks co-resident) ----------------
__device__ __forceinline__ void grid_barrier() {
    __syncthreads();
    if (threadIdx.x == 0) {
        __threadfence();
        int e = *(volatile int*)&g_bar_epoch;
        int t = atomicAdd(&g_bar_count, 1);
        if (t == NBLK - 1) {
            g_bar_count = 0;
            __threadfence();
            atomicAdd(&g_bar_epoch, 1);
        } else {
            while (*(volatile int*)&g_bar_epoch == e) { }
        }
        __threadfence();
    }
    __syncthreads();
}

// ---------------- threefry2x32 (JAX-compatible) ----------------
__device__ __forceinline__ uint32_t rotl32(uint32_t x, int d) {
    return (x << d) | (x >> (32 - d));
}
__device__ __forceinline__ void threefry2x32(uint32_t k0, uint32_t k1,
                                             uint32_t x0, uint32_t x1,
                                             uint32_t& o0, uint32_t& o1) {
    uint32_t ks[3] = {k0, k1, k0 ^ k1 ^ 0x1BD11BDAu};
    x0 += ks[0]; x1 += ks[1];
    const int R[2][4] = {{13, 15, 26, 6}, {17, 29, 16, 24}};
    #pragma unroll
    for (int i = 0; i < 5; i++) {
        const int* r = R[i & 1];
        #pragma unroll
        for (int j = 0; j < 4; j++) {
            x0 += x1; x1 = rotl32(x1, r[j]); x1 ^= x0;
        }
        x0 += ks[(i + 1) % 3];
        x1 += ks[(i + 2) % 3] + (uint32_t)(i + 1);
    }
    o0 = x0; o1 = x1;
}

__device__ __forceinline__ float max4(float4 v) {
    return fmaxf(fmaxf(fabsf(v.x), fabsf(v.y)), fmaxf(fabsf(v.z), fabsf(v.w)));
}

// ============================ THE mega-kernel ============================
__global__ void __launch_bounds__(NTHR, 1)
mega(const float* __restrict__ spikes, const float* __restrict__ w_in,
     const float* __restrict__ w_rec,  const float* __restrict__ unit_w,
     const float* __restrict__ cw1,    const float* __restrict__ cb1,
     const float* __restrict__ cw2,    const float* __restrict__ cb2,
     float* __restrict__ out) {
    const int tid  = threadIdx.x;
    const int bid  = blockIdx.x;
    const int warp = tid >> 5, lane = tid & 31;
    const int gtid = bid * NTHR + tid;

    __shared__ float smA[32], smB[32];
    __shared__ float s_red[32];

    // -------- speculative skip-path output + input max (overlapped) --------
    // Safe: if we fall back, Phase F rewrites every out element.
    float xmax = 0.0f;
    if (gtid < (T_STEPS * N_NEUR) / 4) {
        float4 v = reinterpret_cast<const float4*>(spikes)[gtid];
        float4 o;
        o.x = 1.5f * v.x; o.y = 1.5f * v.y; o.z = 1.5f * v.z; o.w = 1.5f * v.w;
        reinterpret_cast<float4*>(out)[gtid] = o;
        xmax = max4(v);
        // NaN spikes: NaN currents never fire z, and out=1.5*spikes matches
        // the reference identically, so dropping NaN via fmax is benign.
    }

    // -------- Phase A: flat grid-strided max|w_in| (perfectly balanced) ----
    // Certificate: L1max <= N * max|w|, so no-spike if 0.2475*X*N*maxW < 14.
    // fmax drops NaN (benign: NaN weights => NaN currents => z==0 => skip
    // output is still exactly right); +/-Inf propagates => fallback.
    float wmax;
    {
        const float4* wp = reinterpret_cast<const float4*>(w_in);
        float m0 = 0.f, m1 = 0.f, m2 = 0.f, m3 = 0.f;
        int i = gtid;
        for (; i + 3 * NTHREADS_G < W_TOT4; i += 4 * NTHREADS_G) {
            float4 a = __ldcs(wp + i);
            float4 b = __ldcs(wp + i + NTHREADS_G);
            float4 c = __ldcs(wp + i + 2 * NTHREADS_G);
            float4 d = __ldcs(wp + i + 3 * NTHREADS_G);
            m0 = fmaxf(m0, max4(a));
            m1 = fmaxf(m1, max4(b));
            m2 = fmaxf(m2, max4(c));
            m3 = fmaxf(m3, max4(d));
        }
        for (; i < W_TOT4; i += NTHREADS_G)
            m0 = fmaxf(m0, max4(__ldcs(wp + i)));
        wmax = fmaxf(fmaxf(m0, m1), fmaxf(m2, m3));
    }

    // block-level reduction of wmax / xmax
    #pragma unroll
    for (int o = 16; o > 0; o >>= 1) {
        wmax = fmaxf(wmax, __shfl_down_sync(0xFFFFFFFFu, wmax, o));
        xmax = fmaxf(xmax, __shfl_down_sync(0xFFFFFFFFu, xmax, o));
    }
    if (lane == 0) { smA[warp] = wmax; smB[warp] = xmax; }
    __syncthreads();
    if (tid == 0) {
        float A = 0.0f, B = 0.0f;
        #pragma unroll
        for (int w = 0; w < 32; w++) { A = fmaxf(A, smA[w]); B = fmaxf(B, smB[w]); }
        g_partialA[bid] = A;
        g_partialB[bid] = B;
    }

    grid_barrier();

    // every block redundantly reduces the 148 partials -> identical decision
    __shared__ int s_skip;
    {
        float A = 0.0f, B = 0.0f;
        if (tid < NBLK) { A = g_partialA[tid]; B = g_partialB[tid]; }
        #pragma unroll
        for (int o = 16; o > 0; o >>= 1) {
            A = fmaxf(A, __shfl_down_sync(0xFFFFFFFFu, A, o));
            B = fmaxf(B, __shfl_down_sync(0xFFFFFFFFu, B, o));
        }
        if (lane == 0) { smA[warp] = A; smB[warp] = B; }
        __syncthreads();
        if (tid == 0) {
            float W = 0.0f, X = 0.0f;
            #pragma unroll
            for (int w = 0; w < 5; w++) { W = fmaxf(W, smA[w]); X = fmaxf(X, smB[w]); }
            // Until the first spike z==0, so |i_t| <= t*X*(N*W) and
            // v_T - V_LEAK <= 5e-5 * 4950 * X * N * W = 0.2475*X*N*W.
            // If < 14 << 15 = VTH - VLEAK, no neuron can ever spike.
            float bound = 0.2475f * X * (float)N_NEUR * W;
            s_skip = (bound < 14.0f) ? 1 : 0;
        }
        __syncthreads();
    }

    // skip: output was already written speculatively
    if (s_skip) return;

    // ================= Fallback path (correctness only) =================

    // ---- Phase B: input-current GEMM cur[u,t,n] = spikes[t,:].w_in[u,n,:] ----
    for (int idx = gtid; idx < U_UNITS * T_STEPS * N_NEUR; idx += NTHREADS_G) {
        int u = idx / (T_STEPS * N_NEUR);
        int r = idx % (T_STEPS * N_NEUR);
        int t = r / N_NEUR, n = r % N_NEUR;
        const float* sp = spikes + (size_t)t * N_NEUR;
        const float* wr = w_in + ((size_t)u * N_NEUR + n) * N_NEUR;
        float acc = 0.0f;
        #pragma unroll 4
        for (int k = 0; k < N_NEUR; k++) acc += sp[k] * wr[k];
        g_cur[idx] = acc;
    }

    grid_barrier();

    // ---- Phase C: LIF recurrent scan, blocks 0..15 each own a unit ----
    {
        __shared__ unsigned mask[32];
        __shared__ int s_total;
        if (bid < U_UNITS) {
            const int u = bid, n = tid;
            if (n == 0) s_total = 0;
            const float DTM = 5e-5f, DEC = 1.0f - 1e-4f;
            const float VLEAK = -70.0f, VTH = -55.0f, VRST = -70.0f;
            float v = VLEAK, i_syn = 0.0f;
            int count_prev = 0, emitted = 0;
            const float* wr   = w_rec + ((size_t)u * N_NEUR + n) * N_NEUR;
            const float* curp = g_cur + (size_t)u * T_STEPS * N_NEUR + n;
            uint8_t*     zp   = g_z   + (size_t)u * T_STEPS * N_NEUR + n;
            float cur_t = curp[0];
            __syncthreads();
            for (int t = 0; t < T_STEPS; t++) {
                float v_dec = v + DTM * ((VLEAK - v) + i_syn);
                float i_dec = i_syn * DEC;
                bool  z     = (v_dec - VTH) > 0.0f;
                v = z ? VRST : v_dec;
                emitted += (int)z;
                zp[t * N_NEUR] = z ? (uint8_t)1 : (uint8_t)0;
                float rec = 0.0f;
                if (count_prev > 0) {
                    #pragma unroll 1
                    for (int w = 0; w < 32; w++) {
                        unsigned m = mask[w];
                        while (m) {
                            int b = __ffs(m) - 1;
                            rec += wr[w * 32 + b];
                            m &= m - 1;
                        }
                    }
                }
                i_syn = i_dec + cur_t + rec;
                float cur_next = (t + 1 < T_STEPS) ? curp[(t + 1) * N_NEUR] : 0.0f;
                __syncthreads();
                unsigned bal = __ballot_sync(0xFFFFFFFFu, z);
                if (lane == 0) mask[warp] = bal;
                __syncthreads();
                count_prev = 0;
                #pragma unroll
                for (int w = 0; w < 32; w++) count_prev += __popc(mask[w]);
                cur_t = cur_next;
            }
            g_act[u * N_NEUR + n] = (float)emitted * (1.0f / T_STEPS);
            atomicAdd(&s_total, emitted);
            __syncthreads();
            if (n == 0) g_spk[u] = s_total;
        }
    }

    grid_barrier();

    // ---- Phase D: hidden layer h = relu(act @ cw1.T + cb1), blocks 0..127 ----
    if (bid < H_DIM) {
        const float* row = cw1 + (size_t)bid * (U_UNITS * N_NEUR);
        float s = 0.0f;
        for (int j = tid; j < U_UNITS * N_NEUR; j += NTHR) s += row[j] * g_act[j];
        #pragma unroll
        for (int o = 16; o > 0; o >>= 1) s += __shfl_down_sync(0xFFFFFFFFu, s, o);
        if (lane == 0) s_red[warp] = s;
        __syncthreads();
        if (tid == 0) {
            float v = 0.0f;
            #pragma unroll
            for (int w = 0; w < 32; w++) v += s_red[w];
            g_h[bid] = fmaxf(v + cb1[bid], 0.0f);
        }
    }

    grid_barrier();

    // ---- Phase E: conn matrix + spike total, block 0 ----
    if (bid == 0) {
        __shared__ float hs[H_DIM];
        if (tid < H_DIM) hs[tid] = g_h[tid];
        __syncthreads();
        if (tid < U_UNITS * U_UNITS) {
            const int j = tid;
            float logit = cb2[j];
            const float* row = cw2 + (size_t)j * H_DIM;
            #pragma unroll 4
            for (int k = 0; k < H_DIM; k++) logit += hs[k] * row[k];
            float p = 1.0f / (1.0f + expf(-logit));
            uint32_t c = (j < 128) ? (uint32_t)j : (uint32_t)(j - 128);
            uint32_t o0, o1;
            threefry2x32(0u, 42u, c, c + 128u, o0, o1);
            uint32_t bits = (j < 128) ? o0 : o1;
            float uf = __uint_as_float((bits >> 9) | 0x3F800000u) - 1.0f;
            uf = fmaxf(uf, 0.0f);
            g_conn[j] = (uf < p) ? 1.0f : 0.0f;
            if (j == 0) {
                int tot = 0;
                #pragma unroll
                for (int u2 = 0; u2 < U_UNITS; u2++) tot += g_spk[u2];
                g_spk_total = tot;
            }
        }
    }

    grid_barrier();

    // ---- Phase F: routed/applied/combined + residual ----
    {
        const int zero = (g_spk_total == 0);
        for (int idx = gtid; idx < T_STEPS * N_NEUR; idx += NTHREADS_G) {
            int t = idx / N_NEUR, m = idx % N_NEUR;
            float c = 0.0f;
            if (!zero) {
                for (int j = 0; j < U_UNITS; j++) {
                    float cj = 0.0f;
                    for (int nn = 0; nn < N_NEUR; nn++) {
                        float r = 0.0f;
                        #pragma unroll
                        for (int i2 = 0; i2 < U_UNITS; i2++)
                            r += g_conn[i2 * U_UNITS + j] *
                                 (float)g_z[((size_t)i2 * T_STEPS + t) * N_NEUR + nn];
                        cj += r * unit_w[((size_t)j * N_NEUR + nn) * N_NEUR + m];
                    }
                    c += cj;
                }
                c *= (1.0f / U_UNITS);
            }
            out[idx] = c + 1.5f * spikes[idx];
        }
    }
}

// ---------------- launch ----------------
extern "C" void kernel_launch(void* const* d_in, const int* in_sizes, int n_in,
                              void* d_out, int out_size) {
    const float* spikes = (const float*)d_in[0];
    const float* w_in   = (const float*)d_in[1];
    const float* w_rec  = (const float*)d_in[2];
    const float* unit_w = (const float*)d_in[3];
    const float* cw1    = (const float*)d_in[4];
    const float* cb1    = (const float*)d_in[5];
    const float* cw2    = (const float*)d_in[6];
    const float* cb2    = (const float*)d_in[7];
    float* out = (float*)d_out;

    mega<<<NBLK, NTHR>>>(spikes, w_in, w_rec, unit_w, cw1, cb1, cw2, cb2, out);
}

// round 7
// speedup vs baseline: 1.0201x; 1.0025x over previous
#include <cuda_runtime.h>
#include <cstdint>
#include <math_constants.h>

#define T_STEPS 100
#define U_UNITS 16
#define N_NEUR  1024
#define H_DIM   128
#define NBLK    148
#define NTHR    1024
#define NTHREADS_G (NBLK * NTHR)                    // 151552
#define W_TOT4  (U_UNITS * N_NEUR * N_NEUR / 4)     // 4194304 float4s

// ---------------- scratch (device globals; no allocation) ----------------
__device__ float   g_cur[U_UNITS * T_STEPS * N_NEUR];
__device__ uint8_t g_z[U_UNITS * T_STEPS * N_NEUR];
__device__ float   g_act[U_UNITS * N_NEUR];
__device__ float   g_h[H_DIM];
__device__ float   g_conn[U_UNITS * U_UNITS];
__device__ int     g_spk[U_UNITS];
__device__ int     g_spk_total;
__device__ float   g_partialA[NBLK];     // per-block max |w_in|
__device__ float   g_partialB[NBLK];     // per-block max |input|
// software grid barrier state (epoch-based; replay-safe: epoch only grows)
__device__ int     g_bar_count = 0;
__device__ int     g_bar_epoch = 0;

// ---------------- grid barrier (all NBLK blocks co-resident) ----------------
__device__ __forceinline__ void grid_barrier() {
    __syncthreads();
    if (threadIdx.x == 0) {
        __threadfence();
        int e = *(volatile int*)&g_bar_epoch;
        int t = atomicAdd(&g_bar_count, 1);
        if (t == NBLK - 1) {
            g_bar_count = 0;
            __threadfence();
            atomicAdd(&g_bar_epoch, 1);
        } else {
            while (*(volatile int*)&g_bar_epoch == e) { }
        }
        __threadfence();
    }
    __syncthreads();
}

// ---------------- threefry2x32 (JAX-compatible) ----------------
__device__ __forceinline__ uint32_t rotl32(uint32_t x, int d) {
    return (x << d) | (x >> (32 - d));
}
__device__ __forceinline__ void threefry2x32(uint32_t k0, uint32_t k1,
                                             uint32_t x0, uint32_t x1,
                                             uint32_t& o0, uint32_t& o1) {
    uint32_t ks[3] = {k0, k1, k0 ^ k1 ^ 0x1BD11BDAu};
    x0 += ks[0]; x1 += ks[1];
    const int R[2][4] = {{13, 15, 26, 6}, {17, 29, 16, 24}};
    #pragma unroll
    for (int i = 0; i < 5; i++) {
        const int* r = R[i & 1];
        #pragma unroll
        for (int j = 0; j < 4; j++) {
            x0 += x1; x1 = rotl32(x1, r[j]); x1 ^= x0;
        }
        x0 += ks[(i + 1) % 3];
        x1 += ks[(i + 2) % 3] + (uint32_t)(i + 1);
    }
    o0 = x0; o1 = x1;
}

__device__ __forceinline__ float max4(float4 v) {
    return fmaxf(fmaxf(fabsf(v.x), fabsf(v.y)), fmaxf(fabsf(v.z), fabsf(v.w)));
}

// ============================ THE mega-kernel ============================
__global__ void __launch_bounds__(NTHR, 1)
mega(const float* __restrict__ spikes, const float* __restrict__ w_in,
     const float* __restrict__ w_rec,  const float* __restrict__ unit_w,
     const float* __restrict__ cw1,    const float* __restrict__ cb1,
     const float* __restrict__ cw2,    const float* __restrict__ cb2,
     float* __restrict__ out) {
    const int tid  = threadIdx.x;
    const int bid  = blockIdx.x;
    const int warp = tid >> 5, lane = tid & 31;
    const int gtid = bid * NTHR + tid;

    __shared__ float smA[32], smB[32];
    __shared__ float s_red[32];

    // -------- speculative skip-path output + input max (overlapped) --------
    // Safe: if we fall back, Phase F rewrites every out element.
    float xmax = 0.0f;
    if (gtid < (T_STEPS * N_NEUR) / 4) {
        float4 v = reinterpret_cast<const float4*>(spikes)[gtid];
        float4 o;
        o.x = 1.5f * v.x; o.y = 1.5f * v.y; o.z = 1.5f * v.z; o.w = 1.5f * v.w;
        reinterpret_cast<float4*>(out)[gtid] = o;
        xmax = max4(v);
        // NaN spikes: NaN currents never fire z, and out=1.5*spikes matches
        // the reference identically, so dropping NaN via fmax is benign.
    }

    // -------- Phase A: flat grid-strided max|w_in| --------------------------
    // Plain cached loads (evict-normal): the 64 MB w_in footprint fits in the
    // ~126 MB L2, so back-to-back graph replays re-read it at the LTS rate
    // instead of the DRAM rate. Certificate: L1max <= N * max|w|.
    // fmax drops NaN (benign: NaN weights => NaN currents => z==0 => skip
    // output is still exactly right); +/-Inf propagates => fallback.
    float wmax;
    {
        const float4* wp = reinterpret_cast<const float4*>(w_in);
        float m0 = 0.f, m1 = 0.f, m2 = 0.f, m3 = 0.f;
        float m4 = 0.f, m5 = 0.f, m6 = 0.f, m7 = 0.f;
        int i = gtid;
        for (; i + 7 * NTHREADS_G < W_TOT4; i += 8 * NTHREADS_G) {
            float4 a = wp[i];
            float4 b = wp[i + NTHREADS_G];
            float4 c = wp[i + 2 * NTHREADS_G];
            float4 d = wp[i + 3 * NTHREADS_G];
            float4 e = wp[i + 4 * NTHREADS_G];
            float4 f = wp[i + 5 * NTHREADS_G];
            float4 g = wp[i + 6 * NTHREADS_G];
            float4 h = wp[i + 7 * NTHREADS_G];
            m0 = fmaxf(m0, max4(a));
            m1 = fmaxf(m1, max4(b));
            m2 = fmaxf(m2, max4(c));
            m3 = fmaxf(m3, max4(d));
            m4 = fmaxf(m4, max4(e));
            m5 = fmaxf(m5, max4(f));
            m6 = fmaxf(m6, max4(g));
            m7 = fmaxf(m7, max4(h));
        }
        for (; i < W_TOT4; i += NTHREADS_G)
            m0 = fmaxf(m0, max4(wp[i]));
        wmax = fmaxf(fmaxf(fmaxf(m0, m1), fmaxf(m2, m3)),
                     fmaxf(fmaxf(m4, m5), fmaxf(m6, m7)));
    }

    // block-level reduction of wmax / xmax
    #pragma unroll
    for (int o = 16; o > 0; o >>= 1) {
        wmax = fmaxf(wmax, __shfl_down_sync(0xFFFFFFFFu, wmax, o));
        xmax = fmaxf(xmax, __shfl_down_sync(0xFFFFFFFFu, xmax, o));
    }
    if (lane == 0) { smA[warp] = wmax; smB[warp] = xmax; }
    __syncthreads();
    if (tid == 0) {
        float A = 0.0f, B = 0.0f;
        #pragma unroll
        for (int w = 0; w < 32; w++) { A = fmaxf(A, smA[w]); B = fmaxf(B, smB[w]); }
        g_partialA[bid] = A;
        g_partialB[bid] = B;
    }

    grid_barrier();

    // every block redundantly reduces the 148 partials -> identical decision
    __shared__ int s_skip;
    {
        float A = 0.0f, B = 0.0f;
        if (tid < NBLK) { A = g_partialA[tid]; B = g_partialB[tid]; }
        #pragma unroll
        for (int o = 16; o > 0; o >>= 1) {
            A = fmaxf(A, __shfl_down_sync(0xFFFFFFFFu, A, o));
            B = fmaxf(B, __shfl_down_sync(0xFFFFFFFFu, B, o));
        }
        if (lane == 0) { smA[warp] = A; smB[warp] = B; }
        __syncthreads();
        if (tid == 0) {
            float W = 0.0f, X = 0.0f;
            #pragma unroll
            for (int w = 0; w < 5; w++) { W = fmaxf(W, smA[w]); X = fmaxf(X, smB[w]); }
            // Until the first spike z==0, so |i_t| <= t*X*(N*W) and
            // v_T - V_LEAK <= 5e-5 * 4950 * X * N * W = 0.2475*X*N*W.
            // If < 14 << 15 = VTH - VLEAK, no neuron can ever spike.
            float bound = 0.2475f * X * (float)N_NEUR * W;
            s_skip = (bound < 14.0f) ? 1 : 0;
        }
        __syncthreads();
    }

    // skip: output was already written speculatively
    if (s_skip) return;

    // ================= Fallback path (correctness only) =================

    // ---- Phase B: input-current GEMM cur[u,t,n] = spikes[t,:].w_in[u,n,:] ----
    for (int idx = gtid; idx < U_UNITS * T_STEPS * N_NEUR; idx += NTHREADS_G) {
        int u = idx / (T_STEPS * N_NEUR);
        int r = idx % (T_STEPS * N_NEUR);
        int t = r / N_NEUR, n = r % N_NEUR;
        const float* sp = spikes + (size_t)t * N_NEUR;
        const float* wr = w_in + ((size_t)u * N_NEUR + n) * N_NEUR;
        float acc = 0.0f;
        #pragma unroll 4
        for (int k = 0; k < N_NEUR; k++) acc += sp[k] * wr[k];
        g_cur[idx] = acc;
    }

    grid_barrier();

    // ---- Phase C: LIF recurrent scan, blocks 0..15 each own a unit ----
    {
        __shared__ unsigned mask[32];
        __shared__ int s_total;
        if (bid < U_UNITS) {
            const int u = bid, n = tid;
            if (n == 0) s_total = 0;
            const float DTM = 5e-5f, DEC = 1.0f - 1e-4f;
            const float VLEAK = -70.0f, VTH = -55.0f, VRST = -70.0f;
            float v = VLEAK, i_syn = 0.0f;
            int count_prev = 0, emitted = 0;
            const float* wr   = w_rec + ((size_t)u * N_NEUR + n) * N_NEUR;
            const float* curp = g_cur + (size_t)u * T_STEPS * N_NEUR + n;
            uint8_t*     zp   = g_z   + (size_t)u * T_STEPS * N_NEUR + n;
            float cur_t = curp[0];
            __syncthreads();
            for (int t = 0; t < T_STEPS; t++) {
                float v_dec = v + DTM * ((VLEAK - v) + i_syn);
                float i_dec = i_syn * DEC;
                bool  z     = (v_dec - VTH) > 0.0f;
                v = z ? VRST : v_dec;
                emitted += (int)z;
                zp[t * N_NEUR] = z ? (uint8_t)1 : (uint8_t)0;
                float rec = 0.0f;
                if (count_prev > 0) {
                    #pragma unroll 1
                    for (int w = 0; w < 32; w++) {
                        unsigned m = mask[w];
                        while (m) {
                            int b = __ffs(m) - 1;
                            rec += wr[w * 32 + b];
                            m &= m - 1;
                        }
                    }
                }
                i_syn = i_dec + cur_t + rec;
                float cur_next = (t + 1 < T_STEPS) ? curp[(t + 1) * N_NEUR] : 0.0f;
                __syncthreads();
                unsigned bal = __ballot_sync(0xFFFFFFFFu, z);
                if (lane == 0) mask[warp] = bal;
                __syncthreads();
                count_prev = 0;
                #pragma unroll
                for (int w = 0; w < 32; w++) count_prev += __popc(mask[w]);
                cur_t = cur_next;
            }
            g_act[u * N_NEUR + n] = (float)emitted * (1.0f / T_STEPS);
            atomicAdd(&s_total, emitted);
            __syncthreads();
            if (n == 0) g_spk[u] = s_total;
        }
    }

    grid_barrier();

    // ---- Phase D: hidden layer h = relu(act @ cw1.T + cb1), blocks 0..127 ----
    if (bid < H_DIM) {
        const float* row = cw1 + (size_t)bid * (U_UNITS * N_NEUR);
        float s = 0.0f;
        for (int j = tid; j < U_UNITS * N_NEUR; j += NTHR) s += row[j] * g_act[j];
        #pragma unroll
        for (int o = 16; o > 0; o >>= 1) s += __shfl_down_sync(0xFFFFFFFFu, s, o);
        if (lane == 0) s_red[warp] = s;
        __syncthreads();
        if (tid == 0) {
            float v = 0.0f;
            #pragma unroll
            for (int w = 0; w < 32; w++) v += s_red[w];
            g_h[bid] = fmaxf(v + cb1[bid], 0.0f);
        }
    }

    grid_barrier();

    // ---- Phase E: conn matrix + spike total, block 0 ----
    if (bid == 0) {
        __shared__ float hs[H_DIM];
        if (tid < H_DIM) hs[tid] = g_h[tid];
        __syncthreads();
        if (tid < U_UNITS * U_UNITS) {
            const int j = tid;
            float logit = cb2[j];
            const float* row = cw2 + (size_t)j * H_DIM;
            #pragma unroll 4
            for (int k = 0; k < H_DIM; k++) logit += hs[k] * row[k];
            float p = 1.0f / (1.0f + expf(-logit));
            uint32_t c = (j < 128) ? (uint32_t)j : (uint32_t)(j - 128);
            uint32_t o0, o1;
            threefry2x32(0u, 42u, c, c + 128u, o0, o1);
            uint32_t bits = (j < 128) ? o0 : o1;
            float uf = __uint_as_float((bits >> 9) | 0x3F800000u) - 1.0f;
            uf = fmaxf(uf, 0.0f);
            g_conn[j] = (uf < p) ? 1.0f : 0.0f;
            if (j == 0) {
                int tot = 0;
                #pragma unroll
                for (int u2 = 0; u2 < U_UNITS; u2++) tot += g_spk[u2];
                g_spk_total = tot;
            }
        }
    }

    grid_barrier();

    // ---- Phase F: routed/applied/combined + residual ----
    {
        const int zero = (g_spk_total == 0);
        for (int idx = gtid; idx < T_STEPS * N_NEUR; idx += NTHREADS_G) {
            int t = idx / N_NEUR, m = idx % N_NEUR;
            float c = 0.0f;
            if (!zero) {
                for (int j = 0; j < U_UNITS; j++) {
                    float cj = 0.0f;
                    for (int nn = 0; nn < N_NEUR; nn++) {
                        float r = 0.0f;
                        #pragma unroll
                        for (int i2 = 0; i2 < U_UNITS; i2++)
                            r += g_conn[i2 * U_UNITS + j] *
                                 (float)g_z[((size_t)i2 * T_STEPS + t) * N_NEUR + nn];
                        cj += r * unit_w[((size_t)j * N_NEUR + nn) * N_NEUR + m];
                    }
                    c += cj;
                }
                c *= (1.0f / U_UNITS);
            }
            out[idx] = c + 1.5f * spikes[idx];
        }
    }
}

// ---------------- launch ----------------
extern "C" void kernel_launch(void* const* d_in, const int* in_sizes, int n_in,
                              void* d_out, int out_size) {
    const float* spikes = (const float*)d_in[0];
    const float* w_in   = (const float*)d_in[1];
    const float* w_rec  = (const float*)d_in[2];
    const float* unit_w = (const float*)d_in[3];
    const float* cw1    = (const float*)d_in[4];
    const float* cb1    = (const float*)d_in[5];
    const float* cw2    = (const float*)d_in[6];
    const float* cb2    = (const float*)d_in[7];
    float* out = (float*)d_out;

    mega<<<NBLK, NTHR>>>(spikes, w_in, w_rec, unit_w, cw1, cb1, cw2, cb2, out);
}